// round 2
// baseline (speedup 1.0000x reference)
#include <cuda_runtime.h>
#include <math.h>

// Problem constants
#define BATCH 16
#define C     512          // input channels
#define C1    256          // conv output channels
#define HW    4096         // 64*64

// Scratch (allocation-free rule: __device__ globals)
__device__ float g_G[BATCH * C * C];     // Gram matrices X X^T (raw, not /64)
__device__ float g_s[BATCH * C];         // rowsum(X) per channel (raw)
__device__ float g_M[BATCH * C1 * C];    // M = gamma*softmax(E) + W

// ---------------------------------------------------------------------------
// Kernel 1: per-batch Gram matrix G = X X^T  (128x128 tile, 8x8/thread)
// Diagonal tiles also produce the channel rowsums (lane-pair shuffle, det.)
// ---------------------------------------------------------------------------
__global__ __launch_bounds__(256) void gram_kernel(const float* __restrict__ x) {
    const int b  = blockIdx.z;
    const int i0 = blockIdx.y * 128;
    const int j0 = blockIdx.x * 128;
    const bool diag = (blockIdx.x == blockIdx.y);
    const float* __restrict__ X = x + (size_t)b * C * HW;

    __shared__ float As[8][128];
    __shared__ float Bs[8][128];

    const int t  = threadIdx.x;
    const int lr = t >> 1;            // row within tile for loads (0..127)
    const int lk = (t & 1) * 4;       // k-quad offset (0 or 4)
    const int tx = t & 15;            // 8-col group
    const int ty = t >> 4;            // 8-row group

    float acc[8][8];
#pragma unroll
    for (int i = 0; i < 8; i++)
#pragma unroll
        for (int j = 0; j < 8; j++) acc[i][j] = 0.f;

    float rsum = 0.f;  // partial rowsum of row (i0+lr), valid on diag tiles

    for (int k0 = 0; k0 < HW; k0 += 8) {
        const float4 av = *(const float4*)&X[(size_t)(i0 + lr) * HW + k0 + lk];
        const float4 bv = *(const float4*)&X[(size_t)(j0 + lr) * HW + k0 + lk];
        rsum += av.x + av.y + av.z + av.w;   // only used by diag blocks

        __syncthreads();   // previous iteration's compute done
        As[lk + 0][lr] = av.x; As[lk + 1][lr] = av.y;
        As[lk + 2][lr] = av.z; As[lk + 3][lr] = av.w;
        Bs[lk + 0][lr] = bv.x; Bs[lk + 1][lr] = bv.y;
        Bs[lk + 2][lr] = bv.z; Bs[lk + 3][lr] = bv.w;
        __syncthreads();

#pragma unroll
        for (int kk = 0; kk < 8; kk++) {
            float ar[8], br[8];
            *(float4*)(ar)     = *(const float4*)&As[kk][ty * 8];
            *(float4*)(ar + 4) = *(const float4*)&As[kk][ty * 8 + 4];
            *(float4*)(br)     = *(const float4*)&Bs[kk][tx * 8];
            *(float4*)(br + 4) = *(const float4*)&Bs[kk][tx * 8 + 4];
#pragma unroll
            for (int i = 0; i < 8; i++)
#pragma unroll
                for (int j = 0; j < 8; j++)
                    acc[i][j] += ar[i] * br[j];
        }
    }

    // Rowsum: lanes t and t^1 loaded the same row; combine + write (diag only)
    rsum += __shfl_xor_sync(0xffffffffu, rsum, 1);
    if (diag && ((t & 1) == 0)) g_s[b * C + i0 + (t >> 1)] = rsum;

    // Write the 128x128 tile (coalesced float4 pairs)
    float* __restrict__ Gp = g_G + (size_t)b * C * C;
#pragma unroll
    for (int i = 0; i < 8; i++) {
        const int gi = i0 + ty * 8 + i;
        float* row = Gp + (size_t)gi * C + j0 + tx * 8;
        *(float4*)(row)     = make_float4(acc[i][0], acc[i][1], acc[i][2], acc[i][3]);
        *(float4*)(row + 4) = make_float4(acc[i][4], acc[i][5], acc[i][6], acc[i][7]);
    }
}

// ---------------------------------------------------------------------------
// Kernel 2: E = (W G + b s^T)/64, row softmax over 512, M = gamma*A + W
// One block = 16 rows of E (full 512 cols). Thread t owns cols 2t, 2t+1.
// ---------------------------------------------------------------------------
__global__ __launch_bounds__(256) void attn_kernel(const float* __restrict__ w,
                                                   const float* __restrict__ bias,
                                                   const float* __restrict__ gamma) {
    const int b  = blockIdx.y;
    const int r0 = blockIdx.x * 16;
    const float* __restrict__ G  = g_G + (size_t)b * C * C;
    const float* __restrict__ sv = g_s + b * C;

    __shared__ float Gs[8][C];      // 16 KB
    __shared__ float Ws[8][16];
    __shared__ float red[16][8];

    const int t    = threadIdx.x;
    const int c0   = t * 2;
    const int lane = t & 31;
    const int wid  = t >> 5;

    float acc0[16], acc1[16];
#pragma unroll
    for (int r = 0; r < 16; r++) { acc0[r] = 0.f; acc1[r] = 0.f; }

    for (int k0 = 0; k0 < C; k0 += 8) {
        float4 gr[4];
#pragma unroll
        for (int i = 0; i < 4; i++) {
            const int f  = t + i * 256;
            const int kk = f >> 7;
            const int cq = (f & 127) * 4;
            gr[i] = *(const float4*)&G[(size_t)(k0 + kk) * C + cq];
        }
        float wv = 0.f;
        if (t < 128) wv = w[(size_t)(r0 + (t >> 3)) * C + k0 + (t & 7)];

        __syncthreads();
#pragma unroll
        for (int i = 0; i < 4; i++) {
            const int f  = t + i * 256;
            const int kk = f >> 7;
            const int cq = (f & 127) * 4;
            *(float4*)&Gs[kk][cq] = gr[i];
        }
        if (t < 128) Ws[t & 7][t >> 3] = wv;
        __syncthreads();

#pragma unroll
        for (int kk = 0; kk < 8; kk++) {
            const float g0 = Gs[kk][c0];
            const float g1 = Gs[kk][c0 + 1];
#pragma unroll
            for (int r = 0; r < 16; r++) {
                const float ww = Ws[kk][r];
                acc0[r] += ww * g0;
                acc1[r] += ww * g1;
            }
        }
    }

    // E = (acc + b_r * s_c) / 64
    const float inv64 = 1.0f / 64.0f;
    const float s0 = sv[c0];
    const float s1 = sv[c0 + 1];
#pragma unroll
    for (int r = 0; r < 16; r++) {
        const float br_ = bias[r0 + r];
        acc0[r] = (acc0[r] + br_ * s0) * inv64;
        acc1[r] = (acc1[r] + br_ * s1) * inv64;
    }

    // row max (warp shuffle + cross-warp via smem; deterministic)
    float rowmax[16];
#pragma unroll
    for (int r = 0; r < 16; r++) {
        float m = fmaxf(acc0[r], acc1[r]);
#pragma unroll
        for (int o = 16; o > 0; o >>= 1) m = fmaxf(m, __shfl_xor_sync(0xffffffffu, m, o));
        if (lane == 0) red[r][wid] = m;
    }
    __syncthreads();
#pragma unroll
    for (int r = 0; r < 16; r++) {
        float m = red[r][0];
#pragma unroll
        for (int ww = 1; ww < 8; ww++) m = fmaxf(m, red[r][ww]);
        rowmax[r] = m;
    }
    __syncthreads();

    // exp + row sum
    float rowsum[16];
#pragma unroll
    for (int r = 0; r < 16; r++) {
        acc0[r] = __expf(acc0[r] - rowmax[r]);
        acc1[r] = __expf(acc1[r] - rowmax[r]);
        float sm = acc0[r] + acc1[r];
#pragma unroll
        for (int o = 16; o > 0; o >>= 1) sm += __shfl_xor_sync(0xffffffffu, sm, o);
        if (lane == 0) red[r][wid] = sm;
    }
    __syncthreads();
#pragma unroll
    for (int r = 0; r < 16; r++) {
        float sm = 0.f;
#pragma unroll
        for (int ww = 0; ww < 8; ww++) sm += red[r][ww];
        rowsum[r] = sm;
    }

    // M = gamma * softmax + W
    const float gm = gamma[0];
#pragma unroll
    for (int r = 0; r < 16; r++) {
        const float inv = 1.0f / rowsum[r];
        const float2 wv = *(const float2*)&w[(size_t)(r0 + r) * C + c0];
        float2 mv;
        mv.x = gm * acc0[r] * inv + wv.x;
        mv.y = gm * acc1[r] * inv + wv.y;
        *(float2*)&g_M[((size_t)b * C1 + r0 + r) * C + c0] = mv;
    }
}

// ---------------------------------------------------------------------------
// Kernel 3: out = M @ X + b   (256x4096 per batch, K=512; 128x128 tiles)
// ---------------------------------------------------------------------------
__global__ __launch_bounds__(256) void out_kernel(const float* __restrict__ x,
                                                  const float* __restrict__ bias,
                                                  float* __restrict__ out) {
    const int b  = blockIdx.z;
    const int m0 = blockIdx.y * 128;
    const int n0 = blockIdx.x * 128;
    const float* __restrict__ Mp = g_M + (size_t)b * C1 * C;
    const float* __restrict__ X  = x + (size_t)b * C * HW;

    __shared__ float As[8][128];
    __shared__ float Bs[8][128];

    const int t   = threadIdx.x;
    const int alr = t >> 1;
    const int alk = (t & 1) * 4;
    const int bkk = t >> 5;
    const int bnq = (t & 31) * 4;
    const int tx  = t & 15;
    const int ty  = t >> 4;

    float acc[8][8];
#pragma unroll
    for (int i = 0; i < 8; i++)
#pragma unroll
        for (int j = 0; j < 8; j++) acc[i][j] = 0.f;

    for (int k0 = 0; k0 < C; k0 += 8) {
        const float4 av = *(const float4*)&Mp[(size_t)(m0 + alr) * C + k0 + alk];
        const float4 bv = *(const float4*)&X[(size_t)(k0 + bkk) * HW + n0 + bnq];

        __syncthreads();
        As[alk + 0][alr] = av.x; As[alk + 1][alr] = av.y;
        As[alk + 2][alr] = av.z; As[alk + 3][alr] = av.w;
        *(float4*)&Bs[bkk][bnq] = bv;
        __syncthreads();

#pragma unroll
        for (int kk = 0; kk < 8; kk++) {
            float ar[8], br[8];
            *(float4*)(ar)     = *(const float4*)&As[kk][ty * 8];
            *(float4*)(ar + 4) = *(const float4*)&As[kk][ty * 8 + 4];
            *(float4*)(br)     = *(const float4*)&Bs[kk][tx * 8];
            *(float4*)(br + 4) = *(const float4*)&Bs[kk][tx * 8 + 4];
#pragma unroll
            for (int i = 0; i < 8; i++)
#pragma unroll
                for (int j = 0; j < 8; j++)
                    acc[i][j] += ar[i] * br[j];
        }
    }

#pragma unroll
    for (int i = 0; i < 8; i++) {
        const int row = m0 + ty * 8 + i;
        const float bb = bias[row];
        float* op = out + ((size_t)b * C1 + row) * HW + n0 + tx * 8;
        *(float4*)(op)     = make_float4(acc[i][0] + bb, acc[i][1] + bb,
                                         acc[i][2] + bb, acc[i][3] + bb);
        *(float4*)(op + 4) = make_float4(acc[i][4] + bb, acc[i][5] + bb,
                                         acc[i][6] + bb, acc[i][7] + bb);
    }
}

// ---------------------------------------------------------------------------
extern "C" void kernel_launch(void* const* d_in, const int* in_sizes, int n_in,
                              void* d_out, int out_size) {
    const float* x     = (const float*)d_in[0];  // (16,512,64,64)
    const float* w     = (const float*)d_in[1];  // (256,512,1,1)
    const float* bias  = (const float*)d_in[2];  // (256,)
    const float* gamma = (const float*)d_in[3];  // (1,)
    float* out = (float*)d_out;                  // (16,256,64,64)

    gram_kernel<<<dim3(4, 4, BATCH), 256>>>(x);
    attn_kernel<<<dim3(C1 / 16, BATCH), 256>>>(w, bias, gamma);
    out_kernel<<<dim3(HW / 128, C1 / 128, BATCH), 256>>>(x, bias, out);
}

// round 4
// speedup vs baseline: 2.1916x; 2.1916x over previous
#include <cuda_runtime.h>
#include <cuda_bf16.h>
#include <cstdint>
#include <math.h>

// Problem constants
#define BATCH 16
#define C     512
#define C1    256
#define HW    4096

// ---------------------------------------------------------------------------
// Scratch (__device__ globals; allocation-free rule)
// ---------------------------------------------------------------------------
__device__ unsigned short g_X8hi[BATCH * C * HW];   // X hi, [b][c][n]
__device__ unsigned short g_X8lo[BATCH * C * HW];   // X lo
__device__ unsigned short g_Xthi[BATCH * HW * C];   // X^T hi, [b][n][c]
__device__ unsigned short g_Xtlo[BATCH * HW * C];   // X^T lo
__device__ float          g_G[BATCH * C * C];       // Gram X X^T (fp32)
__device__ float          g_s[BATCH * C];           // channel rowsums
__device__ unsigned short g_Mhi[BATCH * C1 * C];    // M = gamma*softmax + W, hi
__device__ unsigned short g_Mlo[BATCH * C1 * C];    // M lo

// ---------------------------------------------------------------------------
// Helpers (compute_100-legal only: mma.sync + cp.async)
// ---------------------------------------------------------------------------
__device__ __forceinline__ uint32_t smem_u32(const void* p) {
    uint32_t a;
    asm("{ .reg .u64 t; cvta.to.shared.u64 t, %1; cvt.u32.u64 %0, t; }" : "=r"(a) : "l"(p));
    return a;
}

#define CP_ASYNC16(saddr, gptr) \
    asm volatile("cp.async.cg.shared.global [%0], [%1], 16;" :: "r"(saddr), "l"(gptr) : "memory")
#define CP_COMMIT() asm volatile("cp.async.commit_group;" ::: "memory")
#define CP_WAIT(N)  asm volatile("cp.async.wait_group %0;" :: "n"(N) : "memory")

__device__ __forceinline__ void mma16816(float* d, const uint32_t* a, const uint32_t* b) {
    asm volatile(
        "mma.sync.aligned.m16n8k16.row.col.f32.bf16.bf16.f32 "
        "{%0,%1,%2,%3}, {%4,%5,%6,%7}, {%8,%9}, {%0,%1,%2,%3};\n"
        : "+f"(d[0]), "+f"(d[1]), "+f"(d[2]), "+f"(d[3])
        : "r"(a[0]), "r"(a[1]), "r"(a[2]), "r"(a[3]), "r"(b[0]), "r"(b[1]));
}

__device__ __forceinline__ void f2hilo(float v, __nv_bfloat16& h, __nv_bfloat16& l) {
    h = __float2bfloat16(v);
    l = __float2bfloat16(v - __bfloat162float(h));
}

// ---------------------------------------------------------------------------
// Kernel 1: prep — X -> bf16 hi/lo (native + transposed) + channel rowsums
// ---------------------------------------------------------------------------
__global__ __launch_bounds__(256) void prep_kernel(const float* __restrict__ x) {
    __shared__ float sm[32][33];
    const int b  = blockIdx.y;
    const int c0 = blockIdx.x * 32;
    const int t  = threadIdx.x;
    const int r  = t >> 3;       // 0..31
    const int qd = t & 7;        // 0..7

    const float* __restrict__ X = x + ((size_t)b * C + c0) * HW;
    __nv_bfloat16* X8h = (__nv_bfloat16*)g_X8hi + ((size_t)b * C + c0) * HW;
    __nv_bfloat16* X8l = (__nv_bfloat16*)g_X8lo + ((size_t)b * C + c0) * HW;
    __nv_bfloat16* Xth = (__nv_bfloat16*)g_Xthi + (size_t)b * HW * C;
    __nv_bfloat16* Xtl = (__nv_bfloat16*)g_Xtlo + (size_t)b * HW * C;

    float rs = 0.f;
    for (int nt = 0; nt < HW / 32; nt++) {
        const int n0 = nt * 32;
        const float4 v = *(const float4*)(X + (size_t)r * HW + n0 + qd * 4);
        rs += v.x + v.y + v.z + v.w;

        {   // native layout hi/lo
            __nv_bfloat16 h0, h1, h2, h3, l0, l1, l2, l3;
            f2hilo(v.x, h0, l0); f2hilo(v.y, h1, l1);
            f2hilo(v.z, h2, l2); f2hilo(v.w, h3, l3);
            const size_t idx = (size_t)r * HW + n0 + qd * 4;
            *(__nv_bfloat162*)(X8h + idx)     = __halves2bfloat162(h0, h1);
            *(__nv_bfloat162*)(X8h + idx + 2) = __halves2bfloat162(h2, h3);
            *(__nv_bfloat162*)(X8l + idx)     = __halves2bfloat162(l0, l1);
            *(__nv_bfloat162*)(X8l + idx + 2) = __halves2bfloat162(l2, l3);
        }

        __syncthreads();
        sm[r][qd * 4 + 0] = v.x; sm[r][qd * 4 + 1] = v.y;
        sm[r][qd * 4 + 2] = v.z; sm[r][qd * 4 + 3] = v.w;
        __syncthreads();

        {   // transposed layout hi/lo: this thread owns n = n0 + r
            __nv_bfloat16 h0, h1, h2, h3, l0, l1, l2, l3;
            f2hilo(sm[qd * 4 + 0][r], h0, l0);
            f2hilo(sm[qd * 4 + 1][r], h1, l1);
            f2hilo(sm[qd * 4 + 2][r], h2, l2);
            f2hilo(sm[qd * 4 + 3][r], h3, l3);
            const size_t idx = (size_t)(n0 + r) * C + c0 + qd * 4;
            *(__nv_bfloat162*)(Xth + idx)     = __halves2bfloat162(h0, h1);
            *(__nv_bfloat162*)(Xth + idx + 2) = __halves2bfloat162(h2, h3);
            *(__nv_bfloat162*)(Xtl + idx)     = __halves2bfloat162(l0, l1);
            *(__nv_bfloat162*)(Xtl + idx + 2) = __halves2bfloat162(l2, l3);
        }
    }

    rs += __shfl_xor_sync(0xffffffffu, rs, 1);
    rs += __shfl_xor_sync(0xffffffffu, rs, 2);
    rs += __shfl_xor_sync(0xffffffffu, rs, 4);
    if (qd == 0) g_s[b * C + c0 + r] = rs;
}

// ---------------------------------------------------------------------------
// HMMA split-precision GEMM. CTA tile 128x128, K-chunk 64, cp.async double buf.
// D = sum_k A[m,k]*B[n,k];  3 passes: hi*hi + hi*lo + lo*hi.
// SRC==0: Gram (A=B=X8, C=g_G, lower triangle + mirror)
// SRC==1: out = M·X^T + bias (A=M, B=Xt, C=out param)
// ---------------------------------------------------------------------------
#define PADROW 144                     // 72 bf16 per row (64 + 8 pad)
#define MATB   (128 * PADROW)          // 18432 B per matrix tile
#define BUFB   (4 * MATB)              // 73728 B per buffer
#define GEMM_SMEM (2 * BUFB)           // 147456 B

template<int KTOT, int SRC>
__global__ __launch_bounds__(256, 1) void gemm_hmma(float* __restrict__ outp,
                                                    const float* __restrict__ bias)
{
    constexpr int NCH = KTOT / 64;
    extern __shared__ char smem[];
    const uint32_t sbase = smem_u32(smem);

    const int bx = blockIdx.x, by = blockIdx.y, b = blockIdx.z;
    if (SRC == 0 && bx > by) return;     // symmetry: lower triangle only
    const int m0 = by * 128, n0 = bx * 128;

    const int t = threadIdx.x, wid = t >> 5, lane = t & 31;
    const int g = lane >> 2, t2 = lane & 3;
    const int wm = wid >> 2, wn = wid & 3;      // warp tile: 64 rows x 32 cols

    const unsigned short *Ahi, *Alo, *Bhi, *Blo;
    float* Cp;
    int lda, ldb, ldc;
    if (SRC == 0) {
        Ahi = g_X8hi + (size_t)b * C * HW;  Alo = g_X8lo + (size_t)b * C * HW;
        Bhi = Ahi;                          Blo = Alo;
        Cp  = g_G + (size_t)b * C * C;
        lda = HW; ldb = HW; ldc = C;
    } else {
        Ahi = g_Mhi + (size_t)b * C1 * C;   Alo = g_Mlo + (size_t)b * C1 * C;
        Bhi = g_Xthi + (size_t)b * HW * C;  Blo = g_Xtlo + (size_t)b * HW * C;
        Cp  = outp + (size_t)b * C1 * HW;
        lda = C; ldb = C; ldc = HW;
    }

    const int q8 = (t & 7) * 8;          // element offset within 64-wide chunk
    const int rb = t >> 3;               // base row (0..31), +32*i

    // ---- async chunk loader ----
    auto issue_chunk = [&](int c) {
        const uint32_t sb = sbase + (uint32_t)(c & 1) * BUFB;
        const int k0 = c * 64;
#pragma unroll
        for (int i = 0; i < 4; i++) {
            const int r = rb + 32 * i;
            const uint32_t so = (uint32_t)r * PADROW + (t & 7) * 16;
            CP_ASYNC16(sb + so,            Ahi + (size_t)(m0 + r) * lda + k0 + q8);
            CP_ASYNC16(sb + MATB + so,     Alo + (size_t)(m0 + r) * lda + k0 + q8);
            CP_ASYNC16(sb + 2*MATB + so,   Bhi + (size_t)(n0 + r) * ldb + k0 + q8);
            CP_ASYNC16(sb + 3*MATB + so,   Blo + (size_t)(n0 + r) * ldb + k0 + q8);
        }
        CP_COMMIT();
    };

    float acc[4][4][4];
#pragma unroll
    for (int mt = 0; mt < 4; mt++)
#pragma unroll
        for (int nt = 0; nt < 4; nt++)
#pragma unroll
            for (int i = 0; i < 4; i++) acc[mt][nt][i] = 0.f;

    issue_chunk(0);

    for (int c = 0; c < NCH; c++) {
        if (c + 1 < NCH) { issue_chunk(c + 1); CP_WAIT(1); }
        else             { CP_WAIT(0); }
        __syncthreads();

        const char* buf = smem + (c & 1) * BUFB;
        const char* Ah = buf + (wm * 64) * PADROW;
        const char* Al = Ah + MATB;
        const char* Bh = buf + 2 * MATB + (wn * 32) * PADROW;
        const char* Bl = Bh + MATB;

#pragma unroll
        for (int ks = 0; ks < 4; ks++) {
            const int kbB = (ks * 16 + t2 * 2) * 2;   // byte offset of k-frag
            uint32_t ah[4][4], al[4][4], bh[4][2], bl[4][2];
#pragma unroll
            for (int mt = 0; mt < 4; mt++) {
                const char* p = Ah + (mt * 16 + g) * PADROW + kbB;
                ah[mt][0] = *(const uint32_t*)(p);
                ah[mt][1] = *(const uint32_t*)(p + 8 * PADROW);
                ah[mt][2] = *(const uint32_t*)(p + 16);
                ah[mt][3] = *(const uint32_t*)(p + 8 * PADROW + 16);
                const char* pl = Al + (mt * 16 + g) * PADROW + kbB;
                al[mt][0] = *(const uint32_t*)(pl);
                al[mt][1] = *(const uint32_t*)(pl + 8 * PADROW);
                al[mt][2] = *(const uint32_t*)(pl + 16);
                al[mt][3] = *(const uint32_t*)(pl + 8 * PADROW + 16);
            }
#pragma unroll
            for (int nt = 0; nt < 4; nt++) {
                const char* p = Bh + (nt * 8 + g) * PADROW + kbB;
                bh[nt][0] = *(const uint32_t*)(p);
                bh[nt][1] = *(const uint32_t*)(p + 16);
                const char* pl = Bl + (nt * 8 + g) * PADROW + kbB;
                bl[nt][0] = *(const uint32_t*)(pl);
                bl[nt][1] = *(const uint32_t*)(pl + 16);
            }
#pragma unroll
            for (int mt = 0; mt < 4; mt++)
#pragma unroll
                for (int nt = 0; nt < 4; nt++) {
                    mma16816(acc[mt][nt], ah[mt], bh[nt]);
                    mma16816(acc[mt][nt], ah[mt], bl[nt]);
                    mma16816(acc[mt][nt], al[mt], bh[nt]);
                }
        }
        __syncthreads();
    }

    // ---- epilogue ----
    if (SRC == 0) {
        const bool mir = (bx < by);
#pragma unroll
        for (int mt = 0; mt < 4; mt++) {
            const int row = m0 + wm * 64 + mt * 16 + g;
#pragma unroll
            for (int nt = 0; nt < 4; nt++) {
                const int col = n0 + wn * 32 + nt * 8 + t2 * 2;
                const float c0 = acc[mt][nt][0], c1 = acc[mt][nt][1];
                const float c2 = acc[mt][nt][2], c3 = acc[mt][nt][3];
                *(float2*)&Cp[(size_t)row * ldc + col]       = make_float2(c0, c1);
                *(float2*)&Cp[(size_t)(row + 8) * ldc + col] = make_float2(c2, c3);
                if (mir) {
                    Cp[(size_t)col * ldc + row]           = c0;
                    Cp[(size_t)(col + 1) * ldc + row]     = c1;
                    Cp[(size_t)col * ldc + row + 8]       = c2;
                    Cp[(size_t)(col + 1) * ldc + row + 8] = c3;
                }
            }
        }
    } else {
#pragma unroll
        for (int mt = 0; mt < 4; mt++) {
            const int row = m0 + wm * 64 + mt * 16 + g;
            const float b0 = bias[row], b8 = bias[row + 8];
#pragma unroll
            for (int nt = 0; nt < 4; nt++) {
                const int col = n0 + wn * 32 + nt * 8 + t2 * 2;
                *(float2*)&Cp[(size_t)row * ldc + col] =
                    make_float2(acc[mt][nt][0] + b0, acc[mt][nt][1] + b0);
                *(float2*)&Cp[(size_t)(row + 8) * ldc + col] =
                    make_float2(acc[mt][nt][2] + b8, acc[mt][nt][3] + b8);
            }
        }
    }
}

// ---------------------------------------------------------------------------
// Kernel 3: attn — E = (W G + b s^T)/64, softmax over C, M = gamma*A + W
// 32 rows per block; emits M in bf16 hi/lo.
// ---------------------------------------------------------------------------
__global__ __launch_bounds__(256) void attn_kernel(const float* __restrict__ w,
                                                   const float* __restrict__ bias,
                                                   const float* __restrict__ gamma) {
    const int b  = blockIdx.y;
    const int r0 = blockIdx.x * 32;
    const float* __restrict__ G  = g_G + (size_t)b * C * C;
    const float* __restrict__ sv = g_s + b * C;

    __shared__ float Gs[8][C];
    __shared__ float Ws[8][32];
    __shared__ float red[32][8];

    const int t    = threadIdx.x;
    const int c0   = t * 2;
    const int lane = t & 31;
    const int wid  = t >> 5;

    float acc0[32], acc1[32];
#pragma unroll
    for (int r = 0; r < 32; r++) { acc0[r] = 0.f; acc1[r] = 0.f; }

    for (int k0 = 0; k0 < C; k0 += 8) {
        float4 gr[4];
#pragma unroll
        for (int i = 0; i < 4; i++) {
            const int f  = t + i * 256;
            const int kk = f >> 7;
            const int cq = (f & 127) * 4;
            gr[i] = *(const float4*)&G[(size_t)(k0 + kk) * C + cq];
        }
        const float wv = w[(size_t)(r0 + (t >> 3)) * C + k0 + (t & 7)];

        __syncthreads();
#pragma unroll
        for (int i = 0; i < 4; i++) {
            const int f  = t + i * 256;
            const int kk = f >> 7;
            const int cq = (f & 127) * 4;
            *(float4*)&Gs[kk][cq] = gr[i];
        }
        Ws[t & 7][t >> 3] = wv;
        __syncthreads();

#pragma unroll
        for (int kk = 0; kk < 8; kk++) {
            const float g0 = Gs[kk][c0];
            const float g1 = Gs[kk][c0 + 1];
#pragma unroll
            for (int r = 0; r < 32; r++) {
                const float ww = Ws[kk][r];
                acc0[r] += ww * g0;
                acc1[r] += ww * g1;
            }
        }
    }

    const float inv64 = 1.0f / 64.0f;
    const float s0 = sv[c0];
    const float s1 = sv[c0 + 1];
#pragma unroll
    for (int r = 0; r < 32; r++) {
        const float br_ = bias[r0 + r];
        acc0[r] = (acc0[r] + br_ * s0) * inv64;
        acc1[r] = (acc1[r] + br_ * s1) * inv64;
    }

    float rowmax[32];
#pragma unroll
    for (int r = 0; r < 32; r++) {
        float m = fmaxf(acc0[r], acc1[r]);
#pragma unroll
        for (int o = 16; o > 0; o >>= 1) m = fmaxf(m, __shfl_xor_sync(0xffffffffu, m, o));
        if (lane == 0) red[r][wid] = m;
    }
    __syncthreads();
#pragma unroll
    for (int r = 0; r < 32; r++) {
        float m = red[r][0];
#pragma unroll
        for (int ww = 1; ww < 8; ww++) m = fmaxf(m, red[r][ww]);
        rowmax[r] = m;
    }
    __syncthreads();

    float rowsum[32];
#pragma unroll
    for (int r = 0; r < 32; r++) {
        acc0[r] = __expf(acc0[r] - rowmax[r]);
        acc1[r] = __expf(acc1[r] - rowmax[r]);
        float sm = acc0[r] + acc1[r];
#pragma unroll
        for (int o = 16; o > 0; o >>= 1) sm += __shfl_xor_sync(0xffffffffu, sm, o);
        if (lane == 0) red[r][wid] = sm;
    }
    __syncthreads();
#pragma unroll
    for (int r = 0; r < 32; r++) {
        float sm = 0.f;
#pragma unroll
        for (int ww = 0; ww < 8; ww++) sm += red[r][ww];
        rowsum[r] = sm;
    }

    const float gm = gamma[0];
    __nv_bfloat16* Mh = (__nv_bfloat16*)g_Mhi;
    __nv_bfloat16* Ml = (__nv_bfloat16*)g_Mlo;
#pragma unroll
    for (int r = 0; r < 32; r++) {
        const float inv = 1.0f / rowsum[r];
        const float2 wv = *(const float2*)&w[(size_t)(r0 + r) * C + c0];
        const float mx = gm * acc0[r] * inv + wv.x;
        const float my = gm * acc1[r] * inv + wv.y;
        __nv_bfloat16 hx, lx, hy, ly;
        f2hilo(mx, hx, lx);
        f2hilo(my, hy, ly);
        const size_t idx = ((size_t)b * C1 + r0 + r) * C + c0;
        *(__nv_bfloat162*)(Mh + idx) = __halves2bfloat162(hx, hy);
        *(__nv_bfloat162*)(Ml + idx) = __halves2bfloat162(lx, ly);
    }
}

// ---------------------------------------------------------------------------
extern "C" void kernel_launch(void* const* d_in, const int* in_sizes, int n_in,
                              void* d_out, int out_size) {
    const float* x     = (const float*)d_in[0];  // (16,512,64,64)
    const float* w     = (const float*)d_in[1];  // (256,512,1,1)
    const float* bias  = (const float*)d_in[2];  // (256,)
    const float* gamma = (const float*)d_in[3];  // (1,)
    float* out = (float*)d_out;                  // (16,256,64,64)

    static bool attr_done = false;
    if (!attr_done) {
        cudaFuncSetAttribute(gemm_hmma<HW, 0>,
                             cudaFuncAttributeMaxDynamicSharedMemorySize, GEMM_SMEM);
        cudaFuncSetAttribute(gemm_hmma<C, 1>,
                             cudaFuncAttributeMaxDynamicSharedMemorySize, GEMM_SMEM);
        attr_done = true;
    }

    // 1) convert + transpose + rowsums
    prep_kernel<<<dim3(C / 32, BATCH), 256>>>(x);

    // 2) Gram: G = X X^T (lower triangle + mirror), K=4096
    gemm_hmma<HW, 0><<<dim3(4, 4, BATCH), 256, GEMM_SMEM>>>(nullptr, nullptr);

    // 3) energy + softmax + M
    attn_kernel<<<dim3(C1 / 32, BATCH), 256>>>(w, bias, gamma);

    // 4) out = M X + bias, K=512
    gemm_hmma<C, 1><<<dim3(HW / 128, C1 / 128, BATCH), 256, GEMM_SMEM>>>(out, bias);
}

// round 5
// speedup vs baseline: 2.2601x; 1.0312x over previous
#include <cuda_runtime.h>
#include <cuda_bf16.h>
#include <cstdint>
#include <math.h>

// Problem constants
#define BATCH 16
#define C     512
#define C1    256
#define HW    4096

// ---------------------------------------------------------------------------
// Scratch (__device__ globals; allocation-free rule)
// ---------------------------------------------------------------------------
__device__ unsigned short g_X8hi[BATCH * C * HW];   // X hi, [b][c][n]   (out-GEMM B)
__device__ unsigned short g_X8lo[BATCH * C * HW];   // X lo
__device__ unsigned short g_Xthi[BATCH * HW * C];   // X^T hi, [b][n][c] (Gram A/B)
__device__ unsigned short g_Xtlo[BATCH * HW * C];   // X^T lo
__device__ float          g_G[BATCH * C * C];       // Gram X X^T (fp32)
__device__ float          g_s[BATCH * C];           // channel rowsums
__device__ unsigned short g_Mthi[BATCH * C * C1];   // M^T hi, [b][c][q] (out-GEMM A)
__device__ unsigned short g_Mtlo[BATCH * C * C1];   // M^T lo

// ---------------------------------------------------------------------------
// Helpers (compute_100-legal: mma.sync + cp.async + ldmatrix)
// ---------------------------------------------------------------------------
__device__ __forceinline__ uint32_t smem_u32(const void* p) {
    uint32_t a;
    asm("{ .reg .u64 t; cvta.to.shared.u64 t, %1; cvt.u32.u64 %0, t; }" : "=r"(a) : "l"(p));
    return a;
}
#define CP_ASYNC16(saddr, gptr) \
    asm volatile("cp.async.cg.shared.global [%0], [%1], 16;" :: "r"(saddr), "l"(gptr) : "memory")
#define CP_COMMIT() asm volatile("cp.async.commit_group;" ::: "memory")
#define CP_WAIT(N)  asm volatile("cp.async.wait_group %0;" :: "n"(N) : "memory")

#define LDSM_T4(r0, r1, r2, r3, addr) \
    asm volatile("ldmatrix.sync.aligned.m8n8.x4.trans.shared.b16 {%0,%1,%2,%3}, [%4];" \
        : "=r"(r0), "=r"(r1), "=r"(r2), "=r"(r3) : "r"(addr))

__device__ __forceinline__ void mma16816(float* d, const uint32_t* a, const uint32_t* b) {
    asm volatile(
        "mma.sync.aligned.m16n8k16.row.col.f32.bf16.bf16.f32 "
        "{%0,%1,%2,%3}, {%4,%5,%6,%7}, {%8,%9}, {%0,%1,%2,%3};\n"
        : "+f"(d[0]), "+f"(d[1]), "+f"(d[2]), "+f"(d[3])
        : "r"(a[0]), "r"(a[1]), "r"(a[2]), "r"(a[3]), "r"(b[0]), "r"(b[1]));
}

__device__ __forceinline__ void f2hilo(float v, __nv_bfloat16& h, __nv_bfloat16& l) {
    h = __float2bfloat16(v);
    l = __float2bfloat16(v - __bfloat162float(h));
}

// ---------------------------------------------------------------------------
// Kernel 1: prep — X -> bf16 hi/lo (native + transposed) + channel rowsums
// ---------------------------------------------------------------------------
__global__ __launch_bounds__(256) void prep_kernel(const float* __restrict__ x) {
    __shared__ float sm[32][33];
    const int b  = blockIdx.y;
    const int c0 = blockIdx.x * 32;
    const int t  = threadIdx.x;
    const int r  = t >> 3;       // 0..31
    const int qd = t & 7;        // 0..7

    const float* __restrict__ X = x + ((size_t)b * C + c0) * HW;
    __nv_bfloat16* X8h = (__nv_bfloat16*)g_X8hi + ((size_t)b * C + c0) * HW;
    __nv_bfloat16* X8l = (__nv_bfloat16*)g_X8lo + ((size_t)b * C + c0) * HW;
    __nv_bfloat16* Xth = (__nv_bfloat16*)g_Xthi + (size_t)b * HW * C;
    __nv_bfloat16* Xtl = (__nv_bfloat16*)g_Xtlo + (size_t)b * HW * C;

    float rs = 0.f;
    for (int nt = 0; nt < HW / 32; nt++) {
        const int n0 = nt * 32;
        const float4 v = *(const float4*)(X + (size_t)r * HW + n0 + qd * 4);
        rs += v.x + v.y + v.z + v.w;

        {   // native layout hi/lo
            __nv_bfloat16 h0, h1, h2, h3, l0, l1, l2, l3;
            f2hilo(v.x, h0, l0); f2hilo(v.y, h1, l1);
            f2hilo(v.z, h2, l2); f2hilo(v.w, h3, l3);
            const size_t idx = (size_t)r * HW + n0 + qd * 4;
            *(__nv_bfloat162*)(X8h + idx)     = __halves2bfloat162(h0, h1);
            *(__nv_bfloat162*)(X8h + idx + 2) = __halves2bfloat162(h2, h3);
            *(__nv_bfloat162*)(X8l + idx)     = __halves2bfloat162(l0, l1);
            *(__nv_bfloat162*)(X8l + idx + 2) = __halves2bfloat162(l2, l3);
        }

        __syncthreads();
        sm[r][qd * 4 + 0] = v.x; sm[r][qd * 4 + 1] = v.y;
        sm[r][qd * 4 + 2] = v.z; sm[r][qd * 4 + 3] = v.w;
        __syncthreads();

        {   // transposed layout hi/lo: this thread owns n = n0 + r
            __nv_bfloat16 h0, h1, h2, h3, l0, l1, l2, l3;
            f2hilo(sm[qd * 4 + 0][r], h0, l0);
            f2hilo(sm[qd * 4 + 1][r], h1, l1);
            f2hilo(sm[qd * 4 + 2][r], h2, l2);
            f2hilo(sm[qd * 4 + 3][r], h3, l3);
            const size_t idx = (size_t)(n0 + r) * C + c0 + qd * 4;
            *(__nv_bfloat162*)(Xth + idx)     = __halves2bfloat162(h0, h1);
            *(__nv_bfloat162*)(Xth + idx + 2) = __halves2bfloat162(h2, h3);
            *(__nv_bfloat162*)(Xtl + idx)     = __halves2bfloat162(l0, l1);
            *(__nv_bfloat162*)(Xtl + idx + 2) = __halves2bfloat162(l2, l3);
        }
    }

    rs += __shfl_xor_sync(0xffffffffu, rs, 1);
    rs += __shfl_xor_sync(0xffffffffu, rs, 2);
    rs += __shfl_xor_sync(0xffffffffu, rs, 4);
    if (qd == 0) g_s[b * C + c0 + r] = rs;
}

// ---------------------------------------------------------------------------
// HMMA split-precision GEMM, occupancy-2 variant.
// CTA tile 128x128, KC=32, all tiles staged k-major [32 k][128 col] (256B rows,
// XOR-swizzled), fragments via ldmatrix.x4.trans.
// D = sum_k A[m,k]*B[n,k]; 3 passes hi*hi + hi*lo + lo*hi.
// SRC==0: Gram (A=B=Xt, C=g_G, lower triangle + mirror), K=4096
// SRC==1: out = Mt^T · X + bias (A=Mt k-major, B=X8 native k-major), K=512
// ---------------------------------------------------------------------------
#define KC    32
#define CHB   8192                 // per-matrix chunk: 32 rows * 256 B
#define BUF2  (4 * CHB)            // Ah, Al, Bh, Bl
#define GSMEM (2 * BUF2)           // 65536 B (double buffer)

template<int KTOT, int SRC>
__global__ __launch_bounds__(256, 2) void gemm_hmma(float* __restrict__ outp,
                                                    const float* __restrict__ bias)
{
    constexpr int NCH = KTOT / KC;
    extern __shared__ char smem[];
    const uint32_t sbase = smem_u32(smem);

    const int bx = blockIdx.x, by = blockIdx.y, b = blockIdx.z;
    if (SRC == 0 && bx > by) return;     // symmetry: lower triangle only
    const int m0 = by * 128, n0 = bx * 128;

    const int t = threadIdx.x, wid = t >> 5, lane = t & 31;
    const int g = lane >> 2, t2 = lane & 3;
    const int wm = wid >> 2, wn = wid & 3;      // warp tile: 64 m x 32 n

    const unsigned short *Ahi, *Alo, *Bhi, *Blo;
    float* Cp;
    int lda, ldb, ldc;
    if (SRC == 0) {
        Ahi = g_Xthi + (size_t)b * HW * C;  Alo = g_Xtlo + (size_t)b * HW * C;
        Bhi = Ahi;                          Blo = Alo;
        Cp  = g_G + (size_t)b * C * C;
        lda = C; ldb = C; ldc = C;
    } else {
        Ahi = g_Mthi + (size_t)b * C * C1;  Alo = g_Mtlo + (size_t)b * C * C1;
        Bhi = g_X8hi + (size_t)b * C * HW;  Blo = g_X8lo + (size_t)b * C * HW;
        Cp  = outp + (size_t)b * C1 * HW;
        lda = C1; ldb = HW; ldc = HW;
    }

    // ---- async chunk loader: 8 x 16B per thread ----
    auto issue_chunk = [&](int c) {
        const uint32_t sb = sbase + (uint32_t)(c & 1) * BUF2;
        const int k0 = c * KC;
#pragma unroll
        for (int i = 0; i < 8; i++) {
            const int mat = i >> 1;                 // constant per unrolled i
            const int rem = (t + i * 256) & 511;
            const int row = rem >> 4, ch = rem & 15;
            const unsigned short* src = (mat == 0) ? Ahi : (mat == 1) ? Alo
                                      : (mat == 2) ? Bhi : Blo;
            const int ld = (mat < 2) ? lda : ldb;
            const int cb = (mat < 2) ? m0 : n0;
            CP_ASYNC16(sb + mat * CHB + row * 256 + ((ch ^ (row & 7)) << 4),
                       src + (size_t)(k0 + row) * ld + cb + ch * 8);
        }
        CP_COMMIT();
    };

    // ldmatrix per-thread invariants
    const int krl = ((lane >> 4) & 1) * 8 + (lane & 7);   // row within k16 group
    const int cl  = (lane >> 3) & 1;                      // chunk-pair select
    const int l7  = lane & 7;
    const uint32_t rofs = (uint32_t)krl * 256;

    float acc[4][4][4];
#pragma unroll
    for (int mt = 0; mt < 4; mt++)
#pragma unroll
        for (int nt = 0; nt < 4; nt++)
#pragma unroll
            for (int i = 0; i < 4; i++) acc[mt][nt][i] = 0.f;

    issue_chunk(0);

    for (int c = 0; c < NCH; c++) {
        if (c + 1 < NCH) { issue_chunk(c + 1); CP_WAIT(1); }
        else             { CP_WAIT(0); }
        __syncthreads();

        const uint32_t buf = sbase + (uint32_t)(c & 1) * BUF2;
#pragma unroll
        for (int ks = 0; ks < 2; ks++) {
            const uint32_t kbase = buf + (uint32_t)ks * 4096 + rofs;
            uint32_t ah[4][4], al[4][4], bh[4][2], bl[4][2];
#pragma unroll
            for (int mt = 0; mt < 4; mt++) {
                const uint32_t sw = (uint32_t)(((wm * 8 + mt * 2 + cl) ^ l7) << 4);
                LDSM_T4(ah[mt][0], ah[mt][1], ah[mt][2], ah[mt][3], kbase + sw);
                LDSM_T4(al[mt][0], al[mt][1], al[mt][2], al[mt][3], kbase + CHB + sw);
            }
#pragma unroll
            for (int p = 0; p < 2; p++) {
                const uint32_t sw = (uint32_t)(((wn * 4 + p * 2 + cl) ^ l7) << 4);
                uint32_t r0, r1, r2, r3;
                LDSM_T4(r0, r1, r2, r3, kbase + 2 * CHB + sw);
                bh[2 * p][0] = r0; bh[2 * p][1] = r2;
                bh[2 * p + 1][0] = r1; bh[2 * p + 1][1] = r3;
                LDSM_T4(r0, r1, r2, r3, kbase + 3 * CHB + sw);
                bl[2 * p][0] = r0; bl[2 * p][1] = r2;
                bl[2 * p + 1][0] = r1; bl[2 * p + 1][1] = r3;
            }
#pragma unroll
            for (int mt = 0; mt < 4; mt++)
#pragma unroll
                for (int nt = 0; nt < 4; nt++) {
                    mma16816(acc[mt][nt], ah[mt], bh[nt]);
                    mma16816(acc[mt][nt], ah[mt], bl[nt]);
                    mma16816(acc[mt][nt], al[mt], bh[nt]);
                }
        }
        __syncthreads();
    }

    // ---- epilogue ----
    if (SRC == 0) {
        const bool mir = (bx < by);
#pragma unroll
        for (int mt = 0; mt < 4; mt++) {
            const int row = m0 + wm * 64 + mt * 16 + g;
#pragma unroll
            for (int nt = 0; nt < 4; nt++) {
                const int col = n0 + wn * 32 + nt * 8 + t2 * 2;
                const float c0v = acc[mt][nt][0], c1v = acc[mt][nt][1];
                const float c2v = acc[mt][nt][2], c3v = acc[mt][nt][3];
                *(float2*)&Cp[(size_t)row * ldc + col]       = make_float2(c0v, c1v);
                *(float2*)&Cp[(size_t)(row + 8) * ldc + col] = make_float2(c2v, c3v);
                if (mir) {
                    Cp[(size_t)col * ldc + row]           = c0v;
                    Cp[(size_t)(col + 1) * ldc + row]     = c1v;
                    Cp[(size_t)col * ldc + row + 8]       = c2v;
                    Cp[(size_t)(col + 1) * ldc + row + 8] = c3v;
                }
            }
        }
    } else {
#pragma unroll
        for (int mt = 0; mt < 4; mt++) {
            const int row = m0 + wm * 64 + mt * 16 + g;
            const float b0 = bias[row], b8 = bias[row + 8];
#pragma unroll
            for (int nt = 0; nt < 4; nt++) {
                const int col = n0 + wn * 32 + nt * 8 + t2 * 2;
                *(float2*)&Cp[(size_t)row * ldc + col] =
                    make_float2(acc[mt][nt][0] + b0, acc[mt][nt][1] + b0);
                *(float2*)&Cp[(size_t)(row + 8) * ldc + col] =
                    make_float2(acc[mt][nt][2] + b8, acc[mt][nt][3] + b8);
            }
        }
    }
}

// ---------------------------------------------------------------------------
// Kernel 3: attn — E = (W G + b s^T)/64, softmax over C, M = gamma*A + W
// 32 q-rows per block; emits M TRANSPOSED ([c][q]) in bf16 hi/lo.
// ---------------------------------------------------------------------------
__global__ __launch_bounds__(256) void attn_kernel(const float* __restrict__ w,
                                                   const float* __restrict__ bias,
                                                   const float* __restrict__ gamma) {
    const int b  = blockIdx.y;
    const int r0 = blockIdx.x * 32;
    const float* __restrict__ G  = g_G + (size_t)b * C * C;
    const float* __restrict__ sv = g_s + b * C;

    __shared__ float Gs[8][C];
    __shared__ float Ws[8][32];
    __shared__ float red[32][8];

    const int t    = threadIdx.x;
    const int c0   = t * 2;
    const int lane = t & 31;
    const int wid  = t >> 5;

    float acc0[32], acc1[32];
#pragma unroll
    for (int r = 0; r < 32; r++) { acc0[r] = 0.f; acc1[r] = 0.f; }

    for (int k0 = 0; k0 < C; k0 += 8) {
        float4 gr[4];
#pragma unroll
        for (int i = 0; i < 4; i++) {
            const int f  = t + i * 256;
            const int kk = f >> 7;
            const int cq = (f & 127) * 4;
            gr[i] = *(const float4*)&G[(size_t)(k0 + kk) * C + cq];
        }
        const float wv = w[(size_t)(r0 + (t >> 3)) * C + k0 + (t & 7)];

        __syncthreads();
#pragma unroll
        for (int i = 0; i < 4; i++) {
            const int f  = t + i * 256;
            const int kk = f >> 7;
            const int cq = (f & 127) * 4;
            *(float4*)&Gs[kk][cq] = gr[i];
        }
        Ws[t & 7][t >> 3] = wv;
        __syncthreads();

#pragma unroll
        for (int kk = 0; kk < 8; kk++) {
            const float g0 = Gs[kk][c0];
            const float g1 = Gs[kk][c0 + 1];
#pragma unroll
            for (int r = 0; r < 32; r++) {
                const float ww = Ws[kk][r];
                acc0[r] += ww * g0;
                acc1[r] += ww * g1;
            }
        }
    }

    const float inv64 = 1.0f / 64.0f;
    const float s0 = sv[c0];
    const float s1 = sv[c0 + 1];
#pragma unroll
    for (int r = 0; r < 32; r++) {
        const float br_ = bias[r0 + r];
        acc0[r] = (acc0[r] + br_ * s0) * inv64;
        acc1[r] = (acc1[r] + br_ * s1) * inv64;
    }

    float rowmax[32];
#pragma unroll
    for (int r = 0; r < 32; r++) {
        float m = fmaxf(acc0[r], acc1[r]);
#pragma unroll
        for (int o = 16; o > 0; o >>= 1) m = fmaxf(m, __shfl_xor_sync(0xffffffffu, m, o));
        if (lane == 0) red[r][wid] = m;
    }
    __syncthreads();
#pragma unroll
    for (int r = 0; r < 32; r++) {
        float m = red[r][0];
#pragma unroll
        for (int ww = 1; ww < 8; ww++) m = fmaxf(m, red[r][ww]);
        rowmax[r] = m;
    }
    __syncthreads();

    float rowsum[32];
#pragma unroll
    for (int r = 0; r < 32; r++) {
        acc0[r] = __expf(acc0[r] - rowmax[r]);
        acc1[r] = __expf(acc1[r] - rowmax[r]);
        float sm = acc0[r] + acc1[r];
#pragma unroll
        for (int o = 16; o > 0; o >>= 1) sm += __shfl_xor_sync(0xffffffffu, sm, o);
        if (lane == 0) red[r][wid] = sm;
    }
    __syncthreads();
#pragma unroll
    for (int r = 0; r < 32; r++) {
        float sm = 0.f;
#pragma unroll
        for (int ww = 0; ww < 8; ww++) sm += red[r][ww];
        rowsum[r] = sm;
    }

    // M^T write: thread owns columns c0, c0+1 of M  => rows c0, c0+1 of M^T.
    // 16B-packed stores along q (r0..r0+31).
    const float gm = gamma[0];
#pragma unroll
    for (int rb = 0; rb < 32; rb += 8) {
        uint4 vh0, vl0, vh1, vl1;
        unsigned short* ph0 = (unsigned short*)&vh0;
        unsigned short* pl0 = (unsigned short*)&vl0;
        unsigned short* ph1 = (unsigned short*)&vh1;
        unsigned short* pl1 = (unsigned short*)&vl1;
#pragma unroll
        for (int j = 0; j < 8; j++) {
            const int r = rb + j;
            const float inv = 1.0f / rowsum[r];
            const float2 wv = *(const float2*)&w[(size_t)(r0 + r) * C + c0];
            const float mx = gm * acc0[r] * inv + wv.x;
            const float my = gm * acc1[r] * inv + wv.y;
            __nv_bfloat16 h, l;
            f2hilo(mx, h, l);
            ph0[j] = *(unsigned short*)&h;  pl0[j] = *(unsigned short*)&l;
            f2hilo(my, h, l);
            ph1[j] = *(unsigned short*)&h;  pl1[j] = *(unsigned short*)&l;
        }
        const size_t base0 = ((size_t)b * C + c0) * C1 + r0 + rb;
        const size_t base1 = ((size_t)b * C + c0 + 1) * C1 + r0 + rb;
        *(uint4*)&g_Mthi[base0] = vh0;
        *(uint4*)&g_Mtlo[base0] = vl0;
        *(uint4*)&g_Mthi[base1] = vh1;
        *(uint4*)&g_Mtlo[base1] = vl1;
    }
}

// ---------------------------------------------------------------------------
extern "C" void kernel_launch(void* const* d_in, const int* in_sizes, int n_in,
                              void* d_out, int out_size) {
    const float* x     = (const float*)d_in[0];  // (16,512,64,64)
    const float* w     = (const float*)d_in[1];  // (256,512,1,1)
    const float* bias  = (const float*)d_in[2];  // (256,)
    const float* gamma = (const float*)d_in[3];  // (1,)
    float* out = (float*)d_out;                  // (16,256,64,64)

    cudaFuncSetAttribute(gemm_hmma<HW, 0>,
                         cudaFuncAttributeMaxDynamicSharedMemorySize, GSMEM);
    cudaFuncSetAttribute(gemm_hmma<C, 1>,
                         cudaFuncAttributeMaxDynamicSharedMemorySize, GSMEM);

    // 1) convert + transpose + rowsums
    prep_kernel<<<dim3(C / 32, BATCH), 256>>>(x);

    // 2) Gram: G = X X^T (lower triangle + mirror), K=4096
    gemm_hmma<HW, 0><<<dim3(4, 4, BATCH), 256, GSMEM>>>(nullptr, nullptr);

    // 3) energy + softmax + M^T (bf16 hi/lo)
    attn_kernel<<<dim3(C1 / 32, BATCH), 256>>>(w, bias, gamma);

    // 4) out = M X + bias, K=512
    gemm_hmma<C, 1><<<dim3(HW / 128, C1 / 128, BATCH), 256, GSMEM>>>(out, bias);
}